// round 1
// baseline (speedup 1.0000x reference)
#include <cuda_runtime.h>
#include <cstdint>

// Problem constants
#define N 256
#define NP (N * N)               // 65536
static const size_t NV = (size_t)N * N * N;  // 16777216

// Scratch: 5 xy-box-filtered moment volumes (sum_i, sum_r, sum_ii, sum_rr, sum_ir)
// __device__ global (no cudaMalloc allowed). 5 * 64MB = 320MB.
__device__ float g_sum[5][16777216];

// ---------------------------------------------------------------------------
// Kernel 1: compute the 5 products and apply the 5x5 box filter in X and Y
// (zero padding), one z-plane per blockIdx.z. Shared-memory tiled.
// ---------------------------------------------------------------------------
#define TILE 32
#define HALO 2
#define TW (TILE + 2 * HALO)     // 36

__global__ __launch_bounds__(1024) void boxxy_kernel(
    const float* __restrict__ img, const float* __restrict__ ref)
{
    __shared__ float si[TW][TW + 1];
    __shared__ float sr[TW][TW + 1];
    __shared__ float hs[5][TW][TILE + 1];

    const int z  = blockIdx.z;
    const int x0 = blockIdx.x * TILE - HALO;
    const int y0 = blockIdx.y * TILE - HALO;
    const int tid = threadIdx.y * 32 + threadIdx.x;
    const size_t zoff = (size_t)z * NP;

    // Cooperative halo load (zero-pad outside the volume)
    for (int i = tid; i < TW * TW; i += 1024) {
        int ly = i / TW, lx = i - ly * TW;
        int gx = x0 + lx, gy = y0 + ly;
        bool in = (gx >= 0) & (gx < N) & (gy >= 0) & (gy < N);
        size_t off = zoff + (size_t)gy * N + gx;
        si[ly][lx] = in ? __ldg(img + off) : 0.0f;
        sr[ly][lx] = in ? __ldg(ref + off) : 0.0f;
    }
    __syncthreads();

    // Horizontal 5-tap sums of all 5 quantities
    for (int i = tid; i < TW * TILE; i += 1024) {
        int ly = i / TILE, lx = i - ly * TILE;
        float a0 = 0.f, a1 = 0.f, a2 = 0.f, a3 = 0.f, a4 = 0.f;
#pragma unroll
        for (int d = 0; d < 5; d++) {
            float vi = si[ly][lx + d];
            float vr = sr[ly][lx + d];
            a0 += vi;
            a1 += vr;
            a2 += vi * vi;
            a3 += vr * vr;
            a4 += vi * vr;
        }
        hs[0][ly][lx] = a0;
        hs[1][ly][lx] = a1;
        hs[2][ly][lx] = a2;
        hs[3][ly][lx] = a3;
        hs[4][ly][lx] = a4;
    }
    __syncthreads();

    // Vertical 5-tap sums; write intermediates
    const int gx = blockIdx.x * TILE + threadIdx.x;
    const int gy = blockIdx.y * TILE + threadIdx.y;
    const size_t off = zoff + (size_t)gy * N + gx;
#pragma unroll
    for (int q = 0; q < 5; q++) {
        float s = 0.f;
#pragma unroll
        for (int d = 0; d < 5; d++) s += hs[q][threadIdx.y + d][threadIdx.x];
        g_sum[q][off] = s;
    }
}

// ---------------------------------------------------------------------------
// Kernel 2: 5-tap z-box of the intermediates + gradients + force epilogue.
// One thread per (x,y) column over a 64-plane z chunk.
// ---------------------------------------------------------------------------
#define ZCHUNK 64

__global__ __launch_bounds__(256) void zbox_final_kernel(
    const float* __restrict__ img, const float* __restrict__ ref,
    float* __restrict__ out)
{
    const int x  = threadIdx.x;        // 0..255
    const int y  = blockIdx.x;         // 0..255
    const int z0 = blockIdx.y * ZCHUNK;
    const size_t base = (size_t)y * N + x;
    const float npix = 125.0f;
    const float inv_npix = 1.0f / 125.0f;

    for (int z = z0; z < z0 + ZCHUNK; z++) {
        // z-box sums (zero outside volume)
        float s[5];
#pragma unroll
        for (int q = 0; q < 5; q++) {
            float acc = 0.f;
#pragma unroll
            for (int d = -2; d <= 2; d++) {
                int zz = z + d;
                if (zz >= 0 && zz < N)
                    acc += __ldg(&g_sum[q][(size_t)zz * NP + base]);
            }
            s[q] = acc;
        }
        const float sum_i = s[0], sum_r = s[1];
        const float sum_ii = s[2], sum_rr = s[3], sum_ir = s[4];

        // Faithful to reference: reference_image_mean uses sum_i (original bug)
        const float mi = sum_i * inv_npix;
        const float mr = mi;

        const float var_r = sum_rr - 2.0f * mr * sum_r + npix * mr * mr;
        const float var_i = sum_ii - 2.0f * mi * sum_i + npix * mi * mi;
        const float cross = sum_ir - mr * sum_i - mi * sum_r + npix * mi * mr;

        const size_t idx = (size_t)z * NP + base;
        const float ci = __ldg(img + idx);
        const float cr = __ldg(ref + idx);

        // gradients (central inside, one-sided at edges), spacing 1
        float gxi, gxr, gyi, gyr, gzi, gzr;
        if (x == 0)            { gxi = __ldg(img + idx + 1) - ci;  gxr = __ldg(ref + idx + 1) - cr; }
        else if (x == N - 1)   { gxi = ci - __ldg(img + idx - 1);  gxr = cr - __ldg(ref + idx - 1); }
        else { gxi = 0.5f * (__ldg(img + idx + 1) - __ldg(img + idx - 1));
               gxr = 0.5f * (__ldg(ref + idx + 1) - __ldg(ref + idx - 1)); }

        if (y == 0)            { gyi = __ldg(img + idx + N) - ci;  gyr = __ldg(ref + idx + N) - cr; }
        else if (y == N - 1)   { gyi = ci - __ldg(img + idx - N);  gyr = cr - __ldg(ref + idx - N); }
        else { gyi = 0.5f * (__ldg(img + idx + N) - __ldg(img + idx - N));
               gyr = 0.5f * (__ldg(ref + idx + N) - __ldg(ref + idx - N)); }

        if (z == 0)            { gzi = __ldg(img + idx + NP) - ci; gzr = __ldg(ref + idx + NP) - cr; }
        else if (z == N - 1)   { gzi = ci - __ldg(img + idx - NP); gzr = cr - __ldg(ref + idx - NP); }
        else { gzi = 0.5f * (__ldg(img + idx + NP) - __ldg(img + idx - NP));
               gzr = 0.5f * (__ldg(ref + idx + NP) - __ldg(ref + idx - NP)); }

        const float gd = 0.5f * (gzi + gzr);   // axis 2 (D)
        const float gh = 0.5f * (gyi + gyr);   // axis 3 (H)
        const float gw = 0.5f * (gxi + gxr);   // axis 4 (W)

        const float factor =
            2.0f * cross / (var_i * var_r + 1e-6f) * (ci - cross / var_r * cr);

        out[idx]          = -factor * gd;
        out[NV + idx]     = -factor * gh;
        out[2 * NV + idx] = -factor * gw;
    }
}

// ---------------------------------------------------------------------------
extern "C" void kernel_launch(void* const* d_in, const int* in_sizes, int n_in,
                              void* d_out, int out_size)
{
    const float* img = (const float*)d_in[0];   // image
    // d_in[1] = mask (unused, faithful to reference)
    const float* ref = (const float*)d_in[2];   // reference_image
    // d_in[3] = reference_mask (unused)
    float* out = (float*)d_out;

    {
        dim3 block(32, 32, 1);
        dim3 grid(N / TILE, N / TILE, N);
        boxxy_kernel<<<grid, block>>>(img, ref);
    }
    {
        dim3 block(N, 1, 1);
        dim3 grid(N, N / ZCHUNK, 1);
        zbox_final_kernel<<<grid, block>>>(img, ref, out);
    }
}